// round 2
// baseline (speedup 1.0000x reference)
#include <cuda_runtime.h>
#include <math.h>

// Per-block partial maxima. Written unconditionally by every reduce block each
// call -> no reset kernel, no atomics, fully deterministic under graph replay.
#define RED_BLOCKS 1184          // 148 SMs * 8 CTAs
#define THREADS 256

__device__ float g_partials[RED_BLOCKS];

__device__ __forceinline__ float block_reduce_max(float m) {
    #pragma unroll
    for (int o = 16; o > 0; o >>= 1)
        m = fmaxf(m, __shfl_xor_sync(0xffffffffu, m, o));
    __shared__ float sm[THREADS / 32];
    int lane = threadIdx.x & 31;
    int w = threadIdx.x >> 5;
    if (lane == 0) sm[w] = m;
    __syncthreads();
    if (w == 0) {
        m = (lane < (THREADS / 32)) ? sm[lane] : 0.0f;
        #pragma unroll
        for (int o = 16; o > 0; o >>= 1)
            m = fmaxf(m, __shfl_xor_sync(0xffffffffu, m, o));
    }
    return m;  // valid in warp 0
}

__device__ __forceinline__ float max4(float4 v) {
    return fmaxf(fmaxf(fabsf(v.x), fabsf(v.y)), fmaxf(fabsf(v.z), fabsf(v.w)));
}

// Pass A: max |x| reduce. Reads the array in REVERSE order so the low ~126MB
// of the input is what remains resident in L2 when this kernel finishes; the
// quantize pass reads forward and hits L2 for that prefix.
__global__ void __launch_bounds__(THREADS)
bq_max_reduce_kernel(const float4* __restrict__ x, long long nvec,
                     const float* __restrict__ xs, long long ntail_base, int ntail) {
    float m = 0.0f;
    const long long step = (long long)gridDim.x * THREADS;
    long long i = blockIdx.x * (long long)THREADS + threadIdx.x;

    // 4x batched independent loads for MLP
    for (; i + 3 * step < nvec; i += 4 * step) {
        float4 v0 = x[nvec - 1 - i];
        float4 v1 = x[nvec - 1 - (i + step)];
        float4 v2 = x[nvec - 1 - (i + 2 * step)];
        float4 v3 = x[nvec - 1 - (i + 3 * step)];
        m = fmaxf(m, fmaxf(fmaxf(max4(v0), max4(v1)), fmaxf(max4(v2), max4(v3))));
    }
    for (; i < nvec; i += step)
        m = fmaxf(m, max4(x[nvec - 1 - i]));

    if (blockIdx.x == 0 && threadIdx.x < (unsigned)ntail)
        m = fmaxf(m, fabsf(xs[ntail_base + threadIdx.x]));

    m = block_reduce_max(m);
    if (threadIdx.x == 0)
        g_partials[blockIdx.x] = m;
}

__device__ __forceinline__ float bq_quant_one(float v, float s, float inv_s) {
    v = (v >= 0.0f) ? fmaxf(v, 1e-10f) : fminf(v, -1e-10f);  // zeros -> +1e-10
    float i = rintf(v * s);                                   // half-to-even
    i = fminf(fmaxf(i, -128.0f), 127.0f);                     // clip to int8 range
    return i * inv_s;                                         // exact pow2 scale
}

__device__ __forceinline__ void stcs4(float4* p, float4 v) {
    asm volatile("st.global.cs.v4.f32 [%0], {%1,%2,%3,%4};"
                 :: "l"(p), "f"(v.x), "f"(v.y), "f"(v.z), "f"(v.w) : "memory");
}

__device__ __forceinline__ float4 quant4(float4 v, float s, float inv_s) {
    v.x = bq_quant_one(v.x, s, inv_s);
    v.y = bq_quant_one(v.y, s, inv_s);
    v.z = bq_quant_one(v.z, s, inv_s);
    v.w = bq_quant_one(v.w, s, inv_s);
    return v;
}

// Pass B: per-CTA prologue reduces the partials (L2-resident, ~5 loads/thread),
// computes the power-of-two scales, then streams quantization forward.
__global__ void __launch_bounds__(THREADS)
bq_quantize_kernel(const float4* __restrict__ x, float4* __restrict__ y,
                   long long nvec,
                   const float* __restrict__ xs, float* __restrict__ ys,
                   long long ntail_base, int ntail) {
    __shared__ float s_sc[2];
    {
        float m = 0.0f;
        for (int p = threadIdx.x; p < RED_BLOCKS; p += THREADS)
            m = fmaxf(m, g_partials[p]);
        m = block_reduce_max(m);
        if (threadIdx.x == 0) {
            float maxv = fmaxf(m, 1e-10f);  // clamp can only raise tiny maxima
            float e = floorf(log2f(maxv));
            e = fminf(fmaxf(e, -128.0f), 127.0f);
            s_sc[0] = exp2f(-e + 6.0f);     // 2^(-e + (bits-2)), bits=8
            s_sc[1] = exp2f(e - 6.0f);
        }
    }
    __syncthreads();
    const float s = s_sc[0], inv_s = s_sc[1];

    const long long step = (long long)gridDim.x * THREADS;
    long long i = blockIdx.x * (long long)THREADS + threadIdx.x;

    for (; i + 3 * step < nvec; i += 4 * step) {
        float4 v0 = x[i];
        float4 v1 = x[i + step];
        float4 v2 = x[i + 2 * step];
        float4 v3 = x[i + 3 * step];
        stcs4(&y[i],            quant4(v0, s, inv_s));
        stcs4(&y[i + step],     quant4(v1, s, inv_s));
        stcs4(&y[i + 2 * step], quant4(v2, s, inv_s));
        stcs4(&y[i + 3 * step], quant4(v3, s, inv_s));
    }
    for (; i < nvec; i += step)
        stcs4(&y[i], quant4(x[i], s, inv_s));

    if (blockIdx.x == 0 && threadIdx.x < (unsigned)ntail)
        ys[ntail_base + threadIdx.x] =
            bq_quant_one(xs[ntail_base + threadIdx.x], s, inv_s);
}

extern "C" void kernel_launch(void* const* d_in, const int* in_sizes, int n_in,
                              void* d_out, int out_size) {
    const float* x = (const float*)d_in[0];
    float* y = (float*)d_out;
    long long n = (long long)in_sizes[0];
    long long nvec = n >> 2;
    long long ntail_base = nvec << 2;
    int ntail = (int)(n - ntail_base);

    bq_max_reduce_kernel<<<RED_BLOCKS, THREADS>>>(
        (const float4*)x, nvec, x, ntail_base, ntail);

    int q_blocks = 148 * 16;
    long long needed = (nvec + THREADS - 1) / THREADS;
    if ((long long)q_blocks > needed && needed > 0) q_blocks = (int)needed;
    if (q_blocks < 1) q_blocks = 1;
    bq_quantize_kernel<<<q_blocks, THREADS>>>(
        (const float4*)x, (float4*)y, nvec, x, y, ntail_base, ntail);
}